// round 14
// baseline (speedup 1.0000x reference)
#include <cuda_runtime.h>
#include <cuda_bf16.h>
#include <math.h>
#include <stdint.h>

#define B_    2
#define S_    2048
#define DM    1024
#define H_    16
#define DK    64
#define TOPK_ 16

// Scratch (allocation-free rule: __device__ globals)
__device__ float g_Q[B_ * S_ * DM];
__device__ float g_K[B_ * S_ * DM];
__device__ float g_V[B_ * S_ * DM];
// bf16 limb buffers: A (activations), B (Wv), C (Wo)
__device__ __nv_bfloat16 g_Ah[B_ * S_ * DM];
__device__ __nv_bfloat16 g_Am[B_ * S_ * DM];
__device__ __nv_bfloat16 g_Al[B_ * S_ * DM];
__device__ __nv_bfloat16 g_Bh[DM * DM];
__device__ __nv_bfloat16 g_Bm[DM * DM];
__device__ __nv_bfloat16 g_Bl[DM * DM];
__device__ __nv_bfloat16 g_Ch[DM * DM];
__device__ __nv_bfloat16 g_Cm[DM * DM];
__device__ __nv_bfloat16 g_Cl[DM * DM];

// ============================ PTX helpers (sm_80+ only) ============================
__device__ __forceinline__ uint32_t smem_u32(const void* p) {
    uint32_t a;
    asm("{ .reg .u64 t; cvta.to.shared.u64 t, %1; cvt.u32.u64 %0, t; }"
        : "=r"(a) : "l"(p));
    return a;
}
#define CP16(dst, src) \
    asm volatile("cp.async.cg.shared.global [%0], [%1], 16;" :: "r"(dst), "l"(src))
#define CP_COMMIT() asm volatile("cp.async.commit_group;" ::: "memory")
#define CP_WAIT(n)  asm volatile("cp.async.wait_group %0;" :: "n"(n) : "memory")

__device__ __forceinline__ void ldsm4(uint32_t& r0, uint32_t& r1, uint32_t& r2,
                                      uint32_t& r3, uint32_t a) {
    asm volatile("ldmatrix.sync.aligned.m8n8.x4.shared.b16 {%0,%1,%2,%3}, [%4];"
                 : "=r"(r0), "=r"(r1), "=r"(r2), "=r"(r3) : "r"(a));
}
__device__ __forceinline__ void mma16816(float* c, const uint32_t* a,
                                         uint32_t b0, uint32_t b1) {
    asm volatile(
        "mma.sync.aligned.m16n8k16.row.col.f32.bf16.bf16.f32 "
        "{%0,%1,%2,%3}, {%4,%5,%6,%7}, {%8,%9}, {%0,%1,%2,%3};"
        : "+f"(c[0]), "+f"(c[1]), "+f"(c[2]), "+f"(c[3])
        : "r"(a[0]), "r"(a[1]), "r"(a[2]), "r"(a[3]), "r"(b0), "r"(b1));
}

// ---- packed fp32x2 helpers ----
__device__ __forceinline__ unsigned long long pk2(float x, float y) {
    unsigned long long r;
    asm("mov.b64 %0, {%1, %2};" : "=l"(r) : "f"(x), "f"(y));
    return r;
}
__device__ __forceinline__ void fma2(unsigned long long& d,
                                     unsigned long long a, unsigned long long b) {
    asm("fma.rn.f32x2 %0, %1, %2, %0;" : "+l"(d) : "l"(a), "l"(b));
}
__device__ __forceinline__ void unpk2(unsigned long long v, float& lo, float& hi) {
    asm("mov.b64 {%0, %1}, %2;" : "=f"(lo), "=f"(hi) : "l"(v));
}

// ---------------------------------------------------------------------------
// Fused front kernel: one launch, 3072 blocks.
// ---------------------------------------------------------------------------
__global__ __launch_bounds__(256, 2) void fused_front(
    const float* __restrict__ query, const float* __restrict__ Wq,
    const float* __restrict__ bq, float* __restrict__ Qout,
    const float* __restrict__ key, const float* __restrict__ Wk,
    const float* __restrict__ bk, float* __restrict__ Kout,
    const float* __restrict__ value,
    __nv_bfloat16* __restrict__ Ah, __nv_bfloat16* __restrict__ Am,
    __nv_bfloat16* __restrict__ Al,
    const float* __restrict__ Wv,
    __nv_bfloat16* __restrict__ Bh, __nv_bfloat16* __restrict__ Bm,
    __nv_bfloat16* __restrict__ Bl,
    const float* __restrict__ Wo,
    __nv_bfloat16* __restrict__ Ch, __nv_bfloat16* __restrict__ Cm,
    __nv_bfloat16* __restrict__ Cl,
    float4* __restrict__ wz)
{
    __shared__ float As[16][132];
    __shared__ float Ws[16][132];

    const int id = blockIdx.x;
    const int tid = threadIdx.x;

    if (id < 512) {
        const float *A, *W, *bias;
        float* C;
        if (id < 256) { A = query; W = Wq; bias = bq; C = Qout; }
        else          { A = key;   W = Wk; bias = bk; C = Kout; }
        const int r = id & 255;
        const int bm = (r >> 3) * 128;
        const int bn = (r & 7) * 128;
        const int tx = tid & 15;
        const int ty = tid >> 4;

        float acc[8][8];
#pragma unroll
        for (int i = 0; i < 8; i++)
#pragma unroll
            for (int j = 0; j < 8; j++) acc[i][j] = 0.f;

        for (int k0 = 0; k0 < DM; k0 += 16) {
#pragma unroll
            for (int rr = 0; rr < 2; rr++) {
                int idx = tid + rr * 256;
                int row = idx >> 2;
                int c4  = idx & 3;
                float4 av = *(const float4*)(A + (size_t)(bm + row) * DM + k0 + c4 * 4);
                float4 wv = *(const float4*)(W + (size_t)(bn + row) * DM + k0 + c4 * 4);
                As[c4 * 4 + 0][row] = av.x; As[c4 * 4 + 1][row] = av.y;
                As[c4 * 4 + 2][row] = av.z; As[c4 * 4 + 3][row] = av.w;
                Ws[c4 * 4 + 0][row] = wv.x; Ws[c4 * 4 + 1][row] = wv.y;
                Ws[c4 * 4 + 2][row] = wv.z; Ws[c4 * 4 + 3][row] = wv.w;
            }
            __syncthreads();

#pragma unroll
            for (int kk = 0; kk < 16; kk++) {
                float4 a0 = *(const float4*)&As[kk][ty * 8];
                float4 a1 = *(const float4*)&As[kk][ty * 8 + 4];
                float4 b0 = *(const float4*)&Ws[kk][tx * 8];
                float4 b1 = *(const float4*)&Ws[kk][tx * 8 + 4];
                float a[8] = {a0.x, a0.y, a0.z, a0.w, a1.x, a1.y, a1.z, a1.w};
                float b[8] = {b0.x, b0.y, b0.z, b0.w, b1.x, b1.y, b1.z, b1.w};
#pragma unroll
                for (int i = 0; i < 8; i++)
#pragma unroll
                    for (int j = 0; j < 8; j++) acc[i][j] += a[i] * b[j];
            }
            __syncthreads();
        }

#pragma unroll
        for (int i = 0; i < 8; i++) {
            float* crow = C + (size_t)(bm + ty * 8 + i) * DM + bn + tx * 8;
#pragma unroll
            for (int j4 = 0; j4 < 2; j4++) {
                float4 o;
                o.x = acc[i][j4 * 4 + 0] + bias[bn + tx * 8 + j4 * 4 + 0];
                o.y = acc[i][j4 * 4 + 1] + bias[bn + tx * 8 + j4 * 4 + 1];
                o.z = acc[i][j4 * 4 + 2] + bias[bn + tx * 8 + j4 * 4 + 2];
                o.w = acc[i][j4 * 4 + 3] + bias[bn + tx * 8 + j4 * 4 + 3];
                *(float4*)(crow + j4 * 4) = o;
            }
        }
    } else if (id < 1024) {
        const size_t n4 = (size_t)B_ * H_ * S_ * S_ / 4;
        size_t i = (size_t)(id - 512) * 256 + tid;
        const size_t stride = (size_t)512 * 256;
        float4 z = make_float4(0.f, 0.f, 0.f, 0.f);
        for (; i < n4; i += stride) wz[i] = z;
    } else {
        const float* x;
        __nv_bfloat16 *h, *m, *l;
        int n, base, nb;
        if (id < 2048)      { x = value; h = Ah; m = Am; l = Al;
                              n = B_ * S_ * DM; base = 1024; nb = 1024; }
        else if (id < 2560) { x = Wv; h = Bh; m = Bm; l = Bl;
                              n = DM * DM; base = 2048; nb = 512; }
        else                { x = Wo; h = Ch; m = Cm; l = Cl;
                              n = DM * DM; base = 2560; nb = 512; }
        int i = (id - base) * 256 + tid;
        int stride = nb * 256;
        for (; i < n; i += stride) {
            float v = x[i];
            __nv_bfloat16 hh = __float2bfloat16(v);
            float r1 = v - __bfloat162float(hh);
            __nv_bfloat16 mm = __float2bfloat16(r1);
            float r2 = r1 - __bfloat162float(mm);
            h[i] = hh; m[i] = mm; l[i] = __float2bfloat16(r2);
        }
    }
}

// ---------------------------------------------------------------------------
// HMMA GEMM (3-limb, 6 products): CTA 128x128, 8 warps (4m x 2n), k-chunk 32,
// cp.async double buffer. (R10-proven version.)
// ---------------------------------------------------------------------------
#define ATILE 10240
#define BUFB  (6 * ATILE)
#define GEMM_SMEM (2 * BUFB)

__device__ __forceinline__ void issue_tiles3(
    uint32_t sdst, const __nv_bfloat16* const* Ap, const __nv_bfloat16* const* Bp,
    int bm, int bn, int kc, int tid)
{
#pragma unroll
    for (int l = 0; l < 3; l++) {
#pragma unroll
        for (int r = 0; r < 2; r++) {
            int idx = tid + r * 256;
            int row = idx >> 2, q = idx & 3;
            uint32_t doff = (uint32_t)(row * 80 + q * 16);
            const void* sa = (const void*)(Ap[l] + (size_t)(bm + row) * DM + kc + q * 8);
            const void* sb = (const void*)(Bp[l] + (size_t)(bn + row) * DM + kc + q * 8);
            CP16(sdst + l * ATILE + doff, sa);
            CP16(sdst + (3 + l) * ATILE + doff, sb);
        }
    }
}

__global__ __launch_bounds__(256) void gemm_hmma3(
    const __nv_bfloat16* __restrict__ Ah, const __nv_bfloat16* __restrict__ Am,
    const __nv_bfloat16* __restrict__ Al, const __nv_bfloat16* __restrict__ Bh,
    const __nv_bfloat16* __restrict__ Bm, const __nv_bfloat16* __restrict__ Bl,
    const float* __restrict__ bias, float* __restrict__ C)
{
    extern __shared__ char smem[];
    const uint32_t sb = smem_u32(smem);
    const int tid = threadIdx.x;
    const int lane = tid & 31;
    const int wid = tid >> 5;
    const int wm = wid >> 1;
    const int wn = wid & 1;
    const int bm = blockIdx.y * 128;
    const int bn = blockIdx.x * 128;

    const __nv_bfloat16* Ap[3] = {Ah, Am, Al};
    const __nv_bfloat16* Bp[3] = {Bh, Bm, Bl};

    float acc[2][8][4];
#pragma unroll
    for (int mi = 0; mi < 2; mi++)
#pragma unroll
        for (int hn = 0; hn < 8; hn++)
#pragma unroll
            for (int r = 0; r < 4; r++) acc[mi][hn][r] = 0.f;

    const uint32_t a_off = (uint32_t)((wm * 32 + (lane & 15)) * 80 + (lane >> 4) * 16);
    const uint32_t b_off = (uint32_t)((wn * 64 + (lane & 7) + (lane >> 4) * 8) * 80
                                      + ((lane >> 3) & 1) * 16);

    issue_tiles3(sb, Ap, Bp, bm, bn, 0, tid);
    CP_COMMIT();

    const int NCH = DM / 32;
    for (int c = 0; c < NCH; c++) {
        const uint32_t base = sb + (uint32_t)(c & 1) * BUFB;
        if (c + 1 < NCH) {
            issue_tiles3(sb + (uint32_t)((c + 1) & 1) * BUFB, Ap, Bp,
                         bm, bn, (c + 1) * 32, tid);
            CP_COMMIT();
            CP_WAIT(1);
        } else {
            CP_WAIT(0);
        }
        __syncthreads();

#pragma unroll
        for (int ks = 0; ks < 2; ks++) {
#pragma unroll
            for (int half = 0; half < 2; half++) {
                uint32_t bf[3][2][4];
#pragma unroll
                for (int lb = 0; lb < 3; lb++)
#pragma unroll
                    for (int g = 0; g < 2; g++)
                        ldsm4(bf[lb][g][0], bf[lb][g][1], bf[lb][g][2], bf[lb][g][3],
                              base + (3 + lb) * ATILE + b_off
                                   + (uint32_t)((half * 2 + g) * 16 * 80 + ks * 32));
#pragma unroll
                for (int la = 0; la < 3; la++) {
                    uint32_t af[2][4];
#pragma unroll
                    for (int mi = 0; mi < 2; mi++)
                        ldsm4(af[mi][0], af[mi][1], af[mi][2], af[mi][3],
                              base + la * ATILE + a_off
                                   + (uint32_t)(mi * 16 * 80 + ks * 32));
#pragma unroll
                    for (int lb = 0; lb < 3; lb++) {
                        if (la + lb < 3) {
#pragma unroll
                            for (int mi = 0; mi < 2; mi++)
#pragma unroll
                                for (int j = 0; j < 4; j++)
                                    mma16816(acc[mi][half * 4 + j], af[mi],
                                             bf[lb][j >> 1][(j & 1) * 2],
                                             bf[lb][j >> 1][(j & 1) * 2 + 1]);
                        }
                    }
                }
            }
        }
        __syncthreads();
    }

#pragma unroll
    for (int mi = 0; mi < 2; mi++) {
#pragma unroll
        for (int hn = 0; hn < 8; hn++) {
            int row = bm + wm * 32 + mi * 16 + (lane >> 2);
            int col = bn + wn * 64 + hn * 8 + (lane & 3) * 2;
            float b0 = bias[col], b1 = bias[col + 1];
            float2 o0 = make_float2(acc[mi][hn][0] + b0, acc[mi][hn][1] + b1);
            float2 o1 = make_float2(acc[mi][hn][2] + b0, acc[mi][hn][3] + b1);
            *(float2*)(C + (size_t)row * DM + col) = o0;
            *(float2*)(C + (size_t)(row + 8) * DM + col) = o1;
        }
    }
}

// ---------------------------------------------------------------------------
// Sorted top-16 insertion (lanes 0..15 hold desc-sorted (v,i); v[15]=min).
// ---------------------------------------------------------------------------
__device__ __forceinline__ void insert16(float& v, int& i, float cv, int cidx, int lane)
{
    unsigned keep = __ballot_sync(0xffffffffu,
        (lane < 16) && (v > cv || (v == cv && i < cidx)));
    int pos = __popc(keep & 0xffffu);
    float vu = __shfl_up_sync(0xffffffffu, v, 1);
    int   iu = __shfl_up_sync(0xffffffffu, i, 1);
    if (lane < 16) {
        if (lane == pos)      { v = cv; i = cidx; }
        else if (lane > pos)  { v = vu; i = iu;  }
    }
}

// ---------------------------------------------------------------------------
// Fused scores -> streaming top-16 -> softmax -> weights scatter ->
// attn = w @ V emitted directly as bf16 limbs.
// Q stored PRE-DUPLICATED in smem as u64 (x,x) pairs: inner loop is
// 3 LDS.128 + 8 FFMA2 per 16 MACs (no pack MOVs). Numerics identical.
// smem: Qd[64][66] u64 (d-major, dup), Ks[64][68] f32, Sc[64][68] f32
// ---------------------------------------------------------------------------
__global__ __launch_bounds__(256) void attn_topk_kernel(
    const float* __restrict__ Q, const float* __restrict__ K,
    const float* __restrict__ V, float* __restrict__ weights,
    __nv_bfloat16* __restrict__ Ah, __nv_bfloat16* __restrict__ Am,
    __nv_bfloat16* __restrict__ Al)
{
    extern __shared__ float sm[];
    unsigned long long* Qd = (unsigned long long*)sm;   // 64*66 u64 = 8448 floats
    float* Ks = sm + 64 * 66 * 2;                       // 64*68
    float* Sc = Ks + 64 * 68;                           // 64*68

    const int b = blockIdx.z;
    const int h = blockIdx.y;
    const int q0 = blockIdx.x * 64;
    const int tid = threadIdx.x;
    const int lane = tid & 31;
    const int wid = tid >> 5;
    const int tx = tid & 15;
    const int ty = tid >> 4;

    // load Q tile transposed, duplicated into u64 lanes; fold in 1/sqrt(64)
#pragma unroll
    for (int r = 0; r < 4; r++) {
        int idx = tid + r * 256;
        int q = idx >> 4, c4 = idx & 15;
        float4 v = *(const float4*)(Q + (size_t)(b * S_ + q0 + q) * DM + h * DK + c4 * 4);
        float x0 = v.x * 0.125f, x1 = v.y * 0.125f;
        float x2 = v.z * 0.125f, x3 = v.w * 0.125f;
        Qd[(c4 * 4 + 0) * 66 + q] = pk2(x0, x0);
        Qd[(c4 * 4 + 1) * 66 + q] = pk2(x1, x1);
        Qd[(c4 * 4 + 2) * 66 + q] = pk2(x2, x2);
        Qd[(c4 * 4 + 3) * 66 + q] = pk2(x3, x3);
    }

    float tv[8];
    int   ti[8];
    float thr[8];
#pragma unroll
    for (int j = 0; j < 8; j++) { tv[j] = -INFINITY; ti[j] = 0x7fffffff; thr[j] = -INFINITY; }

    for (int k0 = 0; k0 < S_; k0 += 64) {
#pragma unroll
        for (int r = 0; r < 4; r++) {
            int idx = tid + r * 256;
            int key = idx >> 4, c4 = idx & 15;
            float4 v = *(const float4*)(K + (size_t)(b * S_ + k0 + key) * DM + h * DK + c4 * 4);
            Ks[(c4 * 4 + 0) * 68 + key] = v.x;
            Ks[(c4 * 4 + 1) * 68 + key] = v.y;
            Ks[(c4 * 4 + 2) * 68 + key] = v.z;
            Ks[(c4 * 4 + 3) * 68 + key] = v.w;
        }
        __syncthreads();

        unsigned long long acc[4][2];
#pragma unroll
        for (int i = 0; i < 4; i++) { acc[i][0] = 0ull; acc[i][1] = 0ull; }

#pragma unroll 16
        for (int kk = 0; kk < 64; kk++) {
            // K pair-packed directly from the 16B load (no MOVs)
            ulonglong2 bb = *(const ulonglong2*)&Ks[kk * 68 + tx * 4];
            // Q duplicated pairs: 2 x LDS.128 give 4 dup-u64s
            ulonglong2 qa = *(const ulonglong2*)&Qd[kk * 66 + ty * 4];
            ulonglong2 qb = *(const ulonglong2*)&Qd[kk * 66 + ty * 4 + 2];
            fma2(acc[0][0], qa.x, bb.x); fma2(acc[0][1], qa.x, bb.y);
            fma2(acc[1][0], qa.y, bb.x); fma2(acc[1][1], qa.y, bb.y);
            fma2(acc[2][0], qb.x, bb.x); fma2(acc[2][1], qb.x, bb.y);
            fma2(acc[3][0], qb.y, bb.x); fma2(acc[3][1], qb.y, bb.y);
        }
#pragma unroll
        for (int i = 0; i < 4; i++) {
            float4 o;
            unpk2(acc[i][0], o.x, o.y);
            unpk2(acc[i][1], o.z, o.w);
            *(float4*)&Sc[(ty * 4 + i) * 68 + tx * 4] = o;
        }
        __syncthreads();

        // hoisted loads: 16 independent LDS, latency overlapped
        float sv0[8], sv1[8];
#pragma unroll
        for (int j = 0; j < 8; j++) {
            int q = wid * 8 + j;
            sv0[j] = Sc[q * 68 + lane];
            sv1[j] = Sc[q * 68 + 32 + lane];
        }

#pragma unroll
        for (int j = 0; j < 8; j++) {
            unsigned m0 = __ballot_sync(0xffffffffu, sv0[j] > thr[j]);
            while (m0) {
                int src = __ffs(m0) - 1; m0 &= m0 - 1;
                float cv = __shfl_sync(0xffffffffu, sv0[j], src);
                if (cv > thr[j]) {
                    insert16(tv[j], ti[j], cv, k0 + src, lane);
                    thr[j] = __shfl_sync(0xffffffffu, tv[j], 15);
                }
            }
            unsigned m1 = __ballot_sync(0xffffffffu, sv1[j] > thr[j]);
            while (m1) {
                int src = __ffs(m1) - 1; m1 &= m1 - 1;
                float cv = __shfl_sync(0xffffffffu, sv1[j], src);
                if (cv > thr[j]) {
                    insert16(tv[j], ti[j], cv, k0 + 32 + src, lane);
                    thr[j] = __shfl_sync(0xffffffffu, tv[j], 15);
                }
            }
        }
    }

#pragma unroll
    for (int j = 0; j < 8; j++) {
        const int q = q0 + wid * 8 + j;
        float m = __shfl_sync(0xffffffffu, tv[j], 0);
        float e = (lane < 16) ? __expf(tv[j] - m) : 0.f;
        float s = e;
#pragma unroll
        for (int off = 8; off > 0; off >>= 1)
            s += __shfl_xor_sync(0xffffffffu, s, off);
        s = __shfl_sync(0xffffffffu, s, 0);
        float w = e / s;

        float* wrow = weights + ((size_t)((b * H_ + h) * S_) + q) * S_;
        if (lane < 16) wrow[ti[j]] = w;

        float a0 = 0.f, a1 = 0.f;
#pragma unroll
        for (int t = 0; t < TOPK_; t++) {
            float wt = __shfl_sync(0xffffffffu, w, t);
            int  idx = __shfl_sync(0xffffffffu, ti[j], t);
            const float* vr = V + (size_t)(b * S_ + idx) * DM + h * DK;
            a0 += wt * vr[lane];
            a1 += wt * vr[lane + 32];
        }
        size_t off0 = (size_t)(b * S_ + q) * DM + h * DK + lane;
        {
            __nv_bfloat16 hh = __float2bfloat16(a0);
            float r1 = a0 - __bfloat162float(hh);
            __nv_bfloat16 mm = __float2bfloat16(r1);
            float r2 = r1 - __bfloat162float(mm);
            Ah[off0] = hh; Am[off0] = mm; Al[off0] = __float2bfloat16(r2);
        }
        {
            __nv_bfloat16 hh = __float2bfloat16(a1);
            float r1 = a1 - __bfloat162float(hh);
            __nv_bfloat16 mm = __float2bfloat16(r1);
            float r2 = r1 - __bfloat162float(mm);
            Ah[off0 + 32] = hh; Am[off0 + 32] = mm; Al[off0 + 32] = __float2bfloat16(r2);
        }
    }
}

// ---------------------------------------------------------------------------
extern "C" void kernel_launch(void* const* d_in, const int* in_sizes, int n_in,
                              void* d_out, int out_size)
{
    const float* query = (const float*)d_in[0];
    const float* key   = (const float*)d_in[1];
    const float* value = (const float*)d_in[2];
    const float* Wq = (const float*)d_in[3];
    const float* bq = (const float*)d_in[4];
    const float* Wk = (const float*)d_in[5];
    const float* bk = (const float*)d_in[6];
    const float* Wv = (const float*)d_in[7];
    const float* bv = (const float*)d_in[8];
    const float* Wo = (const float*)d_in[9];
    const float* bo = (const float*)d_in[10];

    float* out = (float*)d_out;
    float* weights = out + (size_t)B_ * S_ * DM;

    float *Qp, *Kp, *Vp;
    cudaGetSymbolAddress((void**)&Qp, g_Q);
    cudaGetSymbolAddress((void**)&Kp, g_K);
    cudaGetSymbolAddress((void**)&Vp, g_V);
    __nv_bfloat16 *Ah, *Am, *Al, *Bh, *Bm, *Bl, *Ch, *Cm, *Cl;
    cudaGetSymbolAddress((void**)&Ah, g_Ah);
    cudaGetSymbolAddress((void**)&Am, g_Am);
    cudaGetSymbolAddress((void**)&Al, g_Al);
    cudaGetSymbolAddress((void**)&Bh, g_Bh);
    cudaGetSymbolAddress((void**)&Bm, g_Bm);
    cudaGetSymbolAddress((void**)&Bl, g_Bl);
    cudaGetSymbolAddress((void**)&Ch, g_Ch);
    cudaGetSymbolAddress((void**)&Cm, g_Cm);
    cudaGetSymbolAddress((void**)&Cl, g_Cl);

    cudaFuncSetAttribute(gemm_hmma3,
                         cudaFuncAttributeMaxDynamicSharedMemorySize, GEMM_SMEM);
    dim3 ggrid(DM / 128, (B_ * S_) / 128);    // (8, 32)

    // 1. fused front: Q/K GEMMs + weights zero + all input-side splits
    fused_front<<<3072, 256>>>(query, Wq, bq, Qp,
                               key, Wk, bk, Kp,
                               value, Ah, Am, Al,
                               Wv, Bh, Bm, Bl,
                               Wo, Ch, Cm, Cl,
                               (float4*)weights);

    // 2. V projection: HMMA 3-limb
    gemm_hmma3<<<ggrid, 256, GEMM_SMEM>>>(Ah, Am, Al, Bh, Bm, Bl, bv, Vp);

    // 3. fused attention
    size_t smem = (size_t)(64 * 66 * 2 + 2 * 64 * 68) * sizeof(float);  // 68608
    cudaFuncSetAttribute(attn_topk_kernel,
                         cudaFuncAttributeMaxDynamicSharedMemorySize, (int)smem);
    dim3 attn_grid(S_ / 64, H_, B_);
    attn_topk_kernel<<<attn_grid, 256, smem>>>(Qp, Kp, Vp, weights, Ah, Am, Al);

    // 4. output projection: HMMA 3-limb
    gemm_hmma3<<<ggrid, 256, GEMM_SMEM>>>(Ah, Am, Al, Ch, Cm, Cl, bo, out);
}

// round 15
// speedup vs baseline: 1.3006x; 1.3006x over previous
#include <cuda_runtime.h>
#include <cuda_bf16.h>
#include <math.h>
#include <stdint.h>

#define B_    2
#define S_    2048
#define DM    1024
#define H_    16
#define DK    64
#define TOPK_ 16

// Scratch (allocation-free rule: __device__ globals)
__device__ float g_Q[B_ * S_ * DM];
__device__ float g_K[B_ * S_ * DM];
__device__ float g_V[B_ * S_ * DM];
// bf16 limb buffers: A (activations), B (Wv), C (Wo)
__device__ __nv_bfloat16 g_Ah[B_ * S_ * DM];
__device__ __nv_bfloat16 g_Am[B_ * S_ * DM];
__device__ __nv_bfloat16 g_Bh[DM * DM];
__device__ __nv_bfloat16 g_Bm[DM * DM];
__device__ __nv_bfloat16 g_Ch[DM * DM];
__device__ __nv_bfloat16 g_Cm[DM * DM];

// ============================ PTX helpers (sm_80+ only) ============================
__device__ __forceinline__ uint32_t smem_u32(const void* p) {
    uint32_t a;
    asm("{ .reg .u64 t; cvta.to.shared.u64 t, %1; cvt.u32.u64 %0, t; }"
        : "=r"(a) : "l"(p));
    return a;
}
#define CP16(dst, src) \
    asm volatile("cp.async.cg.shared.global [%0], [%1], 16;" :: "r"(dst), "l"(src))
#define CP_COMMIT() asm volatile("cp.async.commit_group;" ::: "memory")
#define CP_WAIT(n)  asm volatile("cp.async.wait_group %0;" :: "n"(n) : "memory")

__device__ __forceinline__ void ldsm4(uint32_t& r0, uint32_t& r1, uint32_t& r2,
                                      uint32_t& r3, uint32_t a) {
    asm volatile("ldmatrix.sync.aligned.m8n8.x4.shared.b16 {%0,%1,%2,%3}, [%4];"
                 : "=r"(r0), "=r"(r1), "=r"(r2), "=r"(r3) : "r"(a));
}
__device__ __forceinline__ void mma16816(float* c, const uint32_t* a,
                                         uint32_t b0, uint32_t b1) {
    asm volatile(
        "mma.sync.aligned.m16n8k16.row.col.f32.bf16.bf16.f32 "
        "{%0,%1,%2,%3}, {%4,%5,%6,%7}, {%8,%9}, {%0,%1,%2,%3};"
        : "+f"(c[0]), "+f"(c[1]), "+f"(c[2]), "+f"(c[3])
        : "r"(a[0]), "r"(a[1]), "r"(a[2]), "r"(a[3]), "r"(b0), "r"(b1));
}

// ---- packed fp32x2 helpers ----
__device__ __forceinline__ unsigned long long pk2(float x, float y) {
    unsigned long long r;
    asm("mov.b64 %0, {%1, %2};" : "=l"(r) : "f"(x), "f"(y));
    return r;
}
__device__ __forceinline__ void fma2(unsigned long long& d,
                                     unsigned long long a, unsigned long long b) {
    asm("fma.rn.f32x2 %0, %1, %2, %0;" : "+l"(d) : "l"(a), "l"(b));
}
__device__ __forceinline__ void unpk2(unsigned long long v, float& lo, float& hi) {
    asm("mov.b64 {%0, %1}, %2;" : "=f"(lo), "=f"(hi) : "l"(v));
}

// ---------------------------------------------------------------------------
// Fused front kernel: one launch, 3072 blocks.
//   [   0, 256)  Q projection (fp32 GEMM)
//   [ 256, 512)  K projection (fp32 GEMM)
//   [ 512,1024)  zero weights region
//   [1024,2048)  split2(value) -> A limbs
//   [2048,2560)  split2(Wv)    -> B limbs
//   [2560,3072)  split2(Wo)    -> C limbs
// ---------------------------------------------------------------------------
__global__ __launch_bounds__(256, 2) void fused_front(
    const float* __restrict__ query, const float* __restrict__ Wq,
    const float* __restrict__ bq, float* __restrict__ Qout,
    const float* __restrict__ key, const float* __restrict__ Wk,
    const float* __restrict__ bk, float* __restrict__ Kout,
    const float* __restrict__ value,
    __nv_bfloat16* __restrict__ Ah, __nv_bfloat16* __restrict__ Am,
    const float* __restrict__ Wv,
    __nv_bfloat16* __restrict__ Bh, __nv_bfloat16* __restrict__ Bm,
    const float* __restrict__ Wo,
    __nv_bfloat16* __restrict__ Ch, __nv_bfloat16* __restrict__ Cm,
    float4* __restrict__ wz)
{
    __shared__ float As[16][132];
    __shared__ float Ws[16][132];

    const int id = blockIdx.x;
    const int tid = threadIdx.x;

    if (id < 512) {
        const float *A, *W, *bias;
        float* C;
        if (id < 256) { A = query; W = Wq; bias = bq; C = Qout; }
        else          { A = key;   W = Wk; bias = bk; C = Kout; }
        const int r = id & 255;
        const int bm = (r >> 3) * 128;
        const int bn = (r & 7) * 128;
        const int tx = tid & 15;
        const int ty = tid >> 4;

        float acc[8][8];
#pragma unroll
        for (int i = 0; i < 8; i++)
#pragma unroll
            for (int j = 0; j < 8; j++) acc[i][j] = 0.f;

        for (int k0 = 0; k0 < DM; k0 += 16) {
#pragma unroll
            for (int rr = 0; rr < 2; rr++) {
                int idx = tid + rr * 256;
                int row = idx >> 2;
                int c4  = idx & 3;
                float4 av = *(const float4*)(A + (size_t)(bm + row) * DM + k0 + c4 * 4);
                float4 wv = *(const float4*)(W + (size_t)(bn + row) * DM + k0 + c4 * 4);
                As[c4 * 4 + 0][row] = av.x; As[c4 * 4 + 1][row] = av.y;
                As[c4 * 4 + 2][row] = av.z; As[c4 * 4 + 3][row] = av.w;
                Ws[c4 * 4 + 0][row] = wv.x; Ws[c4 * 4 + 1][row] = wv.y;
                Ws[c4 * 4 + 2][row] = wv.z; Ws[c4 * 4 + 3][row] = wv.w;
            }
            __syncthreads();

#pragma unroll
            for (int kk = 0; kk < 16; kk++) {
                float4 a0 = *(const float4*)&As[kk][ty * 8];
                float4 a1 = *(const float4*)&As[kk][ty * 8 + 4];
                float4 b0 = *(const float4*)&Ws[kk][tx * 8];
                float4 b1 = *(const float4*)&Ws[kk][tx * 8 + 4];
                float a[8] = {a0.x, a0.y, a0.z, a0.w, a1.x, a1.y, a1.z, a1.w};
                float b[8] = {b0.x, b0.y, b0.z, b0.w, b1.x, b1.y, b1.z, b1.w};
#pragma unroll
                for (int i = 0; i < 8; i++)
#pragma unroll
                    for (int j = 0; j < 8; j++) acc[i][j] += a[i] * b[j];
            }
            __syncthreads();
        }

#pragma unroll
        for (int i = 0; i < 8; i++) {
            float* crow = C + (size_t)(bm + ty * 8 + i) * DM + bn + tx * 8;
#pragma unroll
            for (int j4 = 0; j4 < 2; j4++) {
                float4 o;
                o.x = acc[i][j4 * 4 + 0] + bias[bn + tx * 8 + j4 * 4 + 0];
                o.y = acc[i][j4 * 4 + 1] + bias[bn + tx * 8 + j4 * 4 + 1];
                o.z = acc[i][j4 * 4 + 2] + bias[bn + tx * 8 + j4 * 4 + 2];
                o.w = acc[i][j4 * 4 + 3] + bias[bn + tx * 8 + j4 * 4 + 3];
                *(float4*)(crow + j4 * 4) = o;
            }
        }
    } else if (id < 1024) {
        const size_t n4 = (size_t)B_ * H_ * S_ * S_ / 4;
        size_t i = (size_t)(id - 512) * 256 + tid;
        const size_t stride = (size_t)512 * 256;
        float4 z = make_float4(0.f, 0.f, 0.f, 0.f);
        for (; i < n4; i += stride) wz[i] = z;
    } else {
        const float* x;
        __nv_bfloat16 *h, *m;
        int n, base, nb;
        if (id < 2048)      { x = value; h = Ah; m = Am;
                              n = B_ * S_ * DM; base = 1024; nb = 1024; }
        else if (id < 2560) { x = Wv; h = Bh; m = Bm;
                              n = DM * DM; base = 2048; nb = 512; }
        else                { x = Wo; h = Ch; m = Cm;
                              n = DM * DM; base = 2560; nb = 512; }
        int i = (id - base) * 256 + tid;
        int stride = nb * 256;
        for (; i < n; i += stride) {
            float v = x[i];
            __nv_bfloat16 hh = __float2bfloat16(v);
            float r1 = v - __bfloat162float(hh);
            h[i] = hh; m[i] = __float2bfloat16(r1);
        }
    }
}

// ---------------------------------------------------------------------------
// HMMA GEMM (2-limb, 3 products hh+hm+mh; err ~2^-16, magnitude-only paths).
// CTA 128x128, 8 warps (4m x 2n), k-chunk 32, cp.async double buffer.
// ---------------------------------------------------------------------------
#define ATILE 10240
#define BUFB  (4 * ATILE)        // A limbs 0..1, B limbs 2..3
#define GEMM_SMEM (2 * BUFB)     // 81920

__device__ __forceinline__ void issue_tiles2(
    uint32_t sdst, const __nv_bfloat16* const* Ap, const __nv_bfloat16* const* Bp,
    int bm, int bn, int kc, int tid)
{
#pragma unroll
    for (int l = 0; l < 2; l++) {
#pragma unroll
        for (int r = 0; r < 2; r++) {
            int idx = tid + r * 256;
            int row = idx >> 2, q = idx & 3;
            uint32_t doff = (uint32_t)(row * 80 + q * 16);
            const void* sa = (const void*)(Ap[l] + (size_t)(bm + row) * DM + kc + q * 8);
            const void* sb = (const void*)(Bp[l] + (size_t)(bn + row) * DM + kc + q * 8);
            CP16(sdst + l * ATILE + doff, sa);
            CP16(sdst + (2 + l) * ATILE + doff, sb);
        }
    }
}

__global__ __launch_bounds__(256) void gemm_hmma2(
    const __nv_bfloat16* __restrict__ Ah, const __nv_bfloat16* __restrict__ Am,
    const __nv_bfloat16* __restrict__ Bh, const __nv_bfloat16* __restrict__ Bm,
    const float* __restrict__ bias, float* __restrict__ C)
{
    extern __shared__ char smem[];
    const uint32_t sb = smem_u32(smem);
    const int tid = threadIdx.x;
    const int lane = tid & 31;
    const int wid = tid >> 5;
    const int wm = wid >> 1;
    const int wn = wid & 1;
    const int bm = blockIdx.y * 128;
    const int bn = blockIdx.x * 128;

    const __nv_bfloat16* Ap[2] = {Ah, Am};
    const __nv_bfloat16* Bp[2] = {Bh, Bm};

    float acc[2][8][4];
#pragma unroll
    for (int mi = 0; mi < 2; mi++)
#pragma unroll
        for (int hn = 0; hn < 8; hn++)
#pragma unroll
            for (int r = 0; r < 4; r++) acc[mi][hn][r] = 0.f;

    const uint32_t a_off = (uint32_t)((wm * 32 + (lane & 15)) * 80 + (lane >> 4) * 16);
    const uint32_t b_off = (uint32_t)((wn * 64 + (lane & 7) + (lane >> 4) * 8) * 80
                                      + ((lane >> 3) & 1) * 16);

    issue_tiles2(sb, Ap, Bp, bm, bn, 0, tid);
    CP_COMMIT();

    const int NCH = DM / 32;
    for (int c = 0; c < NCH; c++) {
        const uint32_t base = sb + (uint32_t)(c & 1) * BUFB;
        if (c + 1 < NCH) {
            issue_tiles2(sb + (uint32_t)((c + 1) & 1) * BUFB, Ap, Bp,
                         bm, bn, (c + 1) * 32, tid);
            CP_COMMIT();
            CP_WAIT(1);
        } else {
            CP_WAIT(0);
        }
        __syncthreads();

#pragma unroll
        for (int ks = 0; ks < 2; ks++) {
#pragma unroll
            for (int half = 0; half < 2; half++) {
                uint32_t bf[2][2][4];
#pragma unroll
                for (int lb = 0; lb < 2; lb++)
#pragma unroll
                    for (int g = 0; g < 2; g++)
                        ldsm4(bf[lb][g][0], bf[lb][g][1], bf[lb][g][2], bf[lb][g][3],
                              base + (2 + lb) * ATILE + b_off
                                   + (uint32_t)((half * 2 + g) * 16 * 80 + ks * 32));
#pragma unroll
                for (int la = 0; la < 2; la++) {
                    uint32_t af[2][4];
#pragma unroll
                    for (int mi = 0; mi < 2; mi++)
                        ldsm4(af[mi][0], af[mi][1], af[mi][2], af[mi][3],
                              base + la * ATILE + a_off
                                   + (uint32_t)(mi * 16 * 80 + ks * 32));
#pragma unroll
                    for (int lb = 0; lb < 2; lb++) {
                        if (la + lb < 2) {
#pragma unroll
                            for (int mi = 0; mi < 2; mi++)
#pragma unroll
                                for (int j = 0; j < 4; j++)
                                    mma16816(acc[mi][half * 4 + j], af[mi],
                                             bf[lb][j >> 1][(j & 1) * 2],
                                             bf[lb][j >> 1][(j & 1) * 2 + 1]);
                        }
                    }
                }
            }
        }
        __syncthreads();
    }

#pragma unroll
    for (int mi = 0; mi < 2; mi++) {
#pragma unroll
        for (int hn = 0; hn < 8; hn++) {
            int row = bm + wm * 32 + mi * 16 + (lane >> 2);
            int col = bn + wn * 64 + hn * 8 + (lane & 3) * 2;
            float b0 = bias[col], b1 = bias[col + 1];
            float2 o0 = make_float2(acc[mi][hn][0] + b0, acc[mi][hn][1] + b1);
            float2 o1 = make_float2(acc[mi][hn][2] + b0, acc[mi][hn][3] + b1);
            *(float2*)(C + (size_t)row * DM + col) = o0;
            *(float2*)(C + (size_t)(row + 8) * DM + col) = o1;
        }
    }
}

// ---------------------------------------------------------------------------
// Sorted top-16 insertion (lanes 0..15 hold desc-sorted (v,i); v[15]=min).
// ---------------------------------------------------------------------------
__device__ __forceinline__ void insert16(float& v, int& i, float cv, int cidx, int lane)
{
    unsigned keep = __ballot_sync(0xffffffffu,
        (lane < 16) && (v > cv || (v == cv && i < cidx)));
    int pos = __popc(keep & 0xffffu);
    float vu = __shfl_up_sync(0xffffffffu, v, 1);
    int   iu = __shfl_up_sync(0xffffffffu, i, 1);
    if (lane < 16) {
        if (lane == pos)      { v = cv; i = cidx; }
        else if (lane > pos)  { v = vu; i = iu;  }
    }
}

// ---------------------------------------------------------------------------
// Fused scores -> streaming top-16 -> softmax -> weights scatter ->
// attn = w @ V emitted as bf16 limbs. (Proven 1565us version, frozen.)
// ---------------------------------------------------------------------------
__global__ __launch_bounds__(256) void attn_topk_kernel(
    const float* __restrict__ Q, const float* __restrict__ K,
    const float* __restrict__ V, float* __restrict__ weights,
    __nv_bfloat16* __restrict__ Ah, __nv_bfloat16* __restrict__ Am)
{
    extern __shared__ float sm[];
    float* Qs = sm;                        // 64*68  [d][q]
    float* Ks = Qs + 64 * 68;              // 64*68  [d][key]
    float* Sc = Ks + 64 * 68;              // 64*68  [q][key]

    const int b = blockIdx.z;
    const int h = blockIdx.y;
    const int q0 = blockIdx.x * 64;
    const int tid = threadIdx.x;
    const int lane = tid & 31;
    const int wid = tid >> 5;
    const int tx = tid & 15;
    const int ty = tid >> 4;

#pragma unroll
    for (int r = 0; r < 4; r++) {
        int idx = tid + r * 256;
        int q = idx >> 4, c4 = idx & 15;
        float4 v = *(const float4*)(Q + (size_t)(b * S_ + q0 + q) * DM + h * DK + c4 * 4);
        Qs[(c4 * 4 + 0) * 68 + q] = v.x * 0.125f;
        Qs[(c4 * 4 + 1) * 68 + q] = v.y * 0.125f;
        Qs[(c4 * 4 + 2) * 68 + q] = v.z * 0.125f;
        Qs[(c4 * 4 + 3) * 68 + q] = v.w * 0.125f;
    }

    float tv[8];
    int   ti[8];
    float thr[8];
#pragma unroll
    for (int j = 0; j < 8; j++) { tv[j] = -INFINITY; ti[j] = 0x7fffffff; thr[j] = -INFINITY; }

    for (int k0 = 0; k0 < S_; k0 += 64) {
#pragma unroll
        for (int r = 0; r < 4; r++) {
            int idx = tid + r * 256;
            int key = idx >> 4, c4 = idx & 15;
            float4 v = *(const float4*)(K + (size_t)(b * S_ + k0 + key) * DM + h * DK + c4 * 4);
            Ks[(c4 * 4 + 0) * 68 + key] = v.x;
            Ks[(c4 * 4 + 1) * 68 + key] = v.y;
            Ks[(c4 * 4 + 2) * 68 + key] = v.z;
            Ks[(c4 * 4 + 3) * 68 + key] = v.w;
        }
        __syncthreads();

        unsigned long long acc[4][2];
#pragma unroll
        for (int i = 0; i < 4; i++) { acc[i][0] = 0ull; acc[i][1] = 0ull; }

#pragma unroll 16
        for (int kk = 0; kk < 64; kk++) {
            float4 a4 = *(const float4*)&Qs[kk * 68 + ty * 4];
            float4 b4 = *(const float4*)&Ks[kk * 68 + tx * 4];
            unsigned long long bp0 = pk2(b4.x, b4.y);
            unsigned long long bp1 = pk2(b4.z, b4.w);
            float a[4] = {a4.x, a4.y, a4.z, a4.w};
#pragma unroll
            for (int i = 0; i < 4; i++) {
                unsigned long long ap = pk2(a[i], a[i]);
                fma2(acc[i][0], ap, bp0);
                fma2(acc[i][1], ap, bp1);
            }
        }
#pragma unroll
        for (int i = 0; i < 4; i++) {
            float4 o;
            unpk2(acc[i][0], o.x, o.y);
            unpk2(acc[i][1], o.z, o.w);
            *(float4*)&Sc[(ty * 4 + i) * 68 + tx * 4] = o;
        }
        __syncthreads();

        float sv0[8], sv1[8];
#pragma unroll
        for (int j = 0; j < 8; j++) {
            int q = wid * 8 + j;
            sv0[j] = Sc[q * 68 + lane];
            sv1[j] = Sc[q * 68 + 32 + lane];
        }

#pragma unroll
        for (int j = 0; j < 8; j++) {
            unsigned m0 = __ballot_sync(0xffffffffu, sv0[j] > thr[j]);
            while (m0) {
                int src = __ffs(m0) - 1; m0 &= m0 - 1;
                float cv = __shfl_sync(0xffffffffu, sv0[j], src);
                if (cv > thr[j]) {
                    insert16(tv[j], ti[j], cv, k0 + src, lane);
                    thr[j] = __shfl_sync(0xffffffffu, tv[j], 15);
                }
            }
            unsigned m1 = __ballot_sync(0xffffffffu, sv1[j] > thr[j]);
            while (m1) {
                int src = __ffs(m1) - 1; m1 &= m1 - 1;
                float cv = __shfl_sync(0xffffffffu, sv1[j], src);
                if (cv > thr[j]) {
                    insert16(tv[j], ti[j], cv, k0 + 32 + src, lane);
                    thr[j] = __shfl_sync(0xffffffffu, tv[j], 15);
                }
            }
        }
    }

#pragma unroll
    for (int j = 0; j < 8; j++) {
        const int q = q0 + wid * 8 + j;
        float m = __shfl_sync(0xffffffffu, tv[j], 0);
        float e = (lane < 16) ? __expf(tv[j] - m) : 0.f;
        float s = e;
#pragma unroll
        for (int off = 8; off > 0; off >>= 1)
            s += __shfl_xor_sync(0xffffffffu, s, off);
        s = __shfl_sync(0xffffffffu, s, 0);
        float w = e / s;

        float* wrow = weights + ((size_t)((b * H_ + h) * S_) + q) * S_;
        if (lane < 16) wrow[ti[j]] = w;

        float a0 = 0.f, a1 = 0.f;
#pragma unroll
        for (int t = 0; t < TOPK_; t++) {
            float wt = __shfl_sync(0xffffffffu, w, t);
            int  idx = __shfl_sync(0xffffffffu, ti[j], t);
            const float* vr = V + (size_t)(b * S_ + idx) * DM + h * DK;
            a0 += wt * vr[lane];
            a1 += wt * vr[lane + 32];
        }
        size_t off0 = (size_t)(b * S_ + q) * DM + h * DK + lane;
        {
            __nv_bfloat16 hh = __float2bfloat16(a0);
            float r1 = a0 - __bfloat162float(hh);
            Ah[off0] = hh; Am[off0] = __float2bfloat16(r1);
        }
        {
            __nv_bfloat16 hh = __float2bfloat16(a1);
            float r1 = a1 - __bfloat162float(hh);
            Ah[off0 + 32] = hh; Am[off0 + 32] = __float2bfloat16(r1);
        }
    }
}

// ---------------------------------------------------------------------------
extern "C" void kernel_launch(void* const* d_in, const int* in_sizes, int n_in,
                              void* d_out, int out_size)
{
    const float* query = (const float*)d_in[0];
    const float* key   = (const float*)d_in[1];
    const float* value = (const float*)d_in[2];
    const float* Wq = (const float*)d_in[3];
    const float* bq = (const float*)d_in[4];
    const float* Wk = (const float*)d_in[5];
    const float* bk = (const float*)d_in[6];
    const float* Wv = (const float*)d_in[7];
    const float* bv = (const float*)d_in[8];
    const float* Wo = (const float*)d_in[9];
    const float* bo = (const float*)d_in[10];

    float* out = (float*)d_out;
    float* weights = out + (size_t)B_ * S_ * DM;

    float *Qp, *Kp, *Vp;
    cudaGetSymbolAddress((void**)&Qp, g_Q);
    cudaGetSymbolAddress((void**)&Kp, g_K);
    cudaGetSymbolAddress((void**)&Vp, g_V);
    __nv_bfloat16 *Ah, *Am, *Bh, *Bm, *Ch, *Cm;
    cudaGetSymbolAddress((void**)&Ah, g_Ah);
    cudaGetSymbolAddress((void**)&Am, g_Am);
    cudaGetSymbolAddress((void**)&Bh, g_Bh);
    cudaGetSymbolAddress((void**)&Bm, g_Bm);
    cudaGetSymbolAddress((void**)&Ch, g_Ch);
    cudaGetSymbolAddress((void**)&Cm, g_Cm);

    cudaFuncSetAttribute(gemm_hmma2,
                         cudaFuncAttributeMaxDynamicSharedMemorySize, GEMM_SMEM);
    dim3 ggrid(DM / 128, (B_ * S_) / 128);    // (8, 32)

    // 1. fused front: Q/K GEMMs + weights zero + all input-side splits
    fused_front<<<3072, 256>>>(query, Wq, bq, Qp,
                               key, Wk, bk, Kp,
                               value, Ah, Am,
                               Wv, Bh, Bm,
                               Wo, Ch, Cm,
                               (float4*)weights);

    // 2. V projection: HMMA 2-limb
    gemm_hmma2<<<ggrid, 256, GEMM_SMEM>>>(Ah, Am, Bh, Bm, bv, Vp);

    // 3. fused attention (writes weights + attn-output limbs into A buffers)
    size_t smem = (size_t)(3 * 64 * 68) * sizeof(float);
    cudaFuncSetAttribute(attn_topk_kernel,
                         cudaFuncAttributeMaxDynamicSharedMemorySize, (int)smem);
    dim3 attn_grid(S_ / 64, H_, B_);
    attn_topk_kernel<<<attn_grid, 256, smem>>>(Qp, Kp, Vp, weights, Ah, Am);

    // 4. output projection: HMMA 2-limb
    gemm_hmma2<<<ggrid, 256, GEMM_SMEM>>>(Ah, Am, Ch, Cm, bo, out);
}

// round 16
// speedup vs baseline: 1.3286x; 1.0215x over previous
#include <cuda_runtime.h>
#include <cuda_bf16.h>
#include <math.h>
#include <stdint.h>

#define B_    2
#define S_    2048
#define DM    1024
#define H_    16
#define DK    64
#define TOPK_ 16

// Scratch (allocation-free rule: __device__ globals)
__device__ float g_Q[B_ * S_ * DM];
__device__ float g_K[B_ * S_ * DM];
__device__ float g_V[B_ * S_ * DM];
// bf16 limb buffers: A (activations), B (Wv), C (Wo)
__device__ __nv_bfloat16 g_Ah[B_ * S_ * DM];
__device__ __nv_bfloat16 g_Am[B_ * S_ * DM];
__device__ __nv_bfloat16 g_Bh[DM * DM];
__device__ __nv_bfloat16 g_Bm[DM * DM];
__device__ __nv_bfloat16 g_Ch[DM * DM];
__device__ __nv_bfloat16 g_Cm[DM * DM];

// ============================ PTX helpers (sm_80+ only) ============================
__device__ __forceinline__ uint32_t smem_u32(const void* p) {
    uint32_t a;
    asm("{ .reg .u64 t; cvta.to.shared.u64 t, %1; cvt.u32.u64 %0, t; }"
        : "=r"(a) : "l"(p));
    return a;
}
#define CP16(dst, src) \
    asm volatile("cp.async.cg.shared.global [%0], [%1], 16;" :: "r"(dst), "l"(src))
#define CP_COMMIT() asm volatile("cp.async.commit_group;" ::: "memory")
#define CP_WAIT(n)  asm volatile("cp.async.wait_group %0;" :: "n"(n) : "memory")

__device__ __forceinline__ void ldsm4(uint32_t& r0, uint32_t& r1, uint32_t& r2,
                                      uint32_t& r3, uint32_t a) {
    asm volatile("ldmatrix.sync.aligned.m8n8.x4.shared.b16 {%0,%1,%2,%3}, [%4];"
                 : "=r"(r0), "=r"(r1), "=r"(r2), "=r"(r3) : "r"(a));
}
__device__ __forceinline__ void mma16816(float* c, const uint32_t* a,
                                         uint32_t b0, uint32_t b1) {
    asm volatile(
        "mma.sync.aligned.m16n8k16.row.col.f32.bf16.bf16.f32 "
        "{%0,%1,%2,%3}, {%4,%5,%6,%7}, {%8,%9}, {%0,%1,%2,%3};"
        : "+f"(c[0]), "+f"(c[1]), "+f"(c[2]), "+f"(c[3])
        : "r"(a[0]), "r"(a[1]), "r"(a[2]), "r"(a[3]), "r"(b0), "r"(b1));
}

// ---- packed fp32x2 helpers ----
__device__ __forceinline__ unsigned long long pk2(float x, float y) {
    unsigned long long r;
    asm("mov.b64 %0, {%1, %2};" : "=l"(r) : "f"(x), "f"(y));
    return r;
}
__device__ __forceinline__ void fma2(unsigned long long& d,
                                     unsigned long long a, unsigned long long b) {
    asm("fma.rn.f32x2 %0, %1, %2, %0;" : "+l"(d) : "l"(a), "l"(b));
}
__device__ __forceinline__ void unpk2(unsigned long long v, float& lo, float& hi) {
    asm("mov.b64 {%0, %1}, %2;" : "=f"(lo), "=f"(hi) : "l"(v));
}

// ---------------------------------------------------------------------------
// Fused front kernel: one launch, 3072 blocks.
//   [   0, 256)  Q projection (fp32 GEMM)
//   [ 256, 512)  K projection (fp32 GEMM)
//   [ 512,1024)  zero weights region
//   [1024,2048)  split2(value) -> A limbs
//   [2048,2560)  split2(Wv)    -> B limbs
//   [2560,3072)  split2(Wo)    -> C limbs
// ---------------------------------------------------------------------------
__global__ __launch_bounds__(256, 2) void fused_front(
    const float* __restrict__ query, const float* __restrict__ Wq,
    const float* __restrict__ bq, float* __restrict__ Qout,
    const float* __restrict__ key, const float* __restrict__ Wk,
    const float* __restrict__ bk, float* __restrict__ Kout,
    const float* __restrict__ value,
    __nv_bfloat16* __restrict__ Ah, __nv_bfloat16* __restrict__ Am,
    const float* __restrict__ Wv,
    __nv_bfloat16* __restrict__ Bh, __nv_bfloat16* __restrict__ Bm,
    const float* __restrict__ Wo,
    __nv_bfloat16* __restrict__ Ch, __nv_bfloat16* __restrict__ Cm,
    float4* __restrict__ wz)
{
    __shared__ float As[16][132];
    __shared__ float Ws[16][132];

    const int id = blockIdx.x;
    const int tid = threadIdx.x;

    if (id < 512) {
        const float *A, *W, *bias;
        float* C;
        if (id < 256) { A = query; W = Wq; bias = bq; C = Qout; }
        else          { A = key;   W = Wk; bias = bk; C = Kout; }
        const int r = id & 255;
        const int bm = (r >> 3) * 128;
        const int bn = (r & 7) * 128;
        const int tx = tid & 15;
        const int ty = tid >> 4;

        float acc[8][8];
#pragma unroll
        for (int i = 0; i < 8; i++)
#pragma unroll
            for (int j = 0; j < 8; j++) acc[i][j] = 0.f;

        for (int k0 = 0; k0 < DM; k0 += 16) {
#pragma unroll
            for (int rr = 0; rr < 2; rr++) {
                int idx = tid + rr * 256;
                int row = idx >> 2;
                int c4  = idx & 3;
                float4 av = *(const float4*)(A + (size_t)(bm + row) * DM + k0 + c4 * 4);
                float4 wv = *(const float4*)(W + (size_t)(bn + row) * DM + k0 + c4 * 4);
                As[c4 * 4 + 0][row] = av.x; As[c4 * 4 + 1][row] = av.y;
                As[c4 * 4 + 2][row] = av.z; As[c4 * 4 + 3][row] = av.w;
                Ws[c4 * 4 + 0][row] = wv.x; Ws[c4 * 4 + 1][row] = wv.y;
                Ws[c4 * 4 + 2][row] = wv.z; Ws[c4 * 4 + 3][row] = wv.w;
            }
            __syncthreads();

#pragma unroll
            for (int kk = 0; kk < 16; kk++) {
                float4 a0 = *(const float4*)&As[kk][ty * 8];
                float4 a1 = *(const float4*)&As[kk][ty * 8 + 4];
                float4 b0 = *(const float4*)&Ws[kk][tx * 8];
                float4 b1 = *(const float4*)&Ws[kk][tx * 8 + 4];
                float a[8] = {a0.x, a0.y, a0.z, a0.w, a1.x, a1.y, a1.z, a1.w};
                float b[8] = {b0.x, b0.y, b0.z, b0.w, b1.x, b1.y, b1.z, b1.w};
#pragma unroll
                for (int i = 0; i < 8; i++)
#pragma unroll
                    for (int j = 0; j < 8; j++) acc[i][j] += a[i] * b[j];
            }
            __syncthreads();
        }

#pragma unroll
        for (int i = 0; i < 8; i++) {
            float* crow = C + (size_t)(bm + ty * 8 + i) * DM + bn + tx * 8;
#pragma unroll
            for (int j4 = 0; j4 < 2; j4++) {
                float4 o;
                o.x = acc[i][j4 * 4 + 0] + bias[bn + tx * 8 + j4 * 4 + 0];
                o.y = acc[i][j4 * 4 + 1] + bias[bn + tx * 8 + j4 * 4 + 1];
                o.z = acc[i][j4 * 4 + 2] + bias[bn + tx * 8 + j4 * 4 + 2];
                o.w = acc[i][j4 * 4 + 3] + bias[bn + tx * 8 + j4 * 4 + 3];
                *(float4*)(crow + j4 * 4) = o;
            }
        }
    } else if (id < 1024) {
        const size_t n4 = (size_t)B_ * H_ * S_ * S_ / 4;
        size_t i = (size_t)(id - 512) * 256 + tid;
        const size_t stride = (size_t)512 * 256;
        float4 z = make_float4(0.f, 0.f, 0.f, 0.f);
        for (; i < n4; i += stride) wz[i] = z;
    } else {
        const float* x;
        __nv_bfloat16 *h, *m;
        int n, base, nb;
        if (id < 2048)      { x = value; h = Ah; m = Am;
                              n = B_ * S_ * DM; base = 1024; nb = 1024; }
        else if (id < 2560) { x = Wv; h = Bh; m = Bm;
                              n = DM * DM; base = 2048; nb = 512; }
        else                { x = Wo; h = Ch; m = Cm;
                              n = DM * DM; base = 2560; nb = 512; }
        int i = (id - base) * 256 + tid;
        int stride = nb * 256;
        for (; i < n; i += stride) {
            float v = x[i];
            __nv_bfloat16 hh = __float2bfloat16(v);
            float r1 = v - __bfloat162float(hh);
            h[i] = hh; m[i] = __float2bfloat16(r1);
        }
    }
}

// ---------------------------------------------------------------------------
// HMMA GEMM (2-limb, 3 products hh+hm+mh; err ~2^-16, magnitude-only paths).
// CTA 128x128, 8 warps (4m x 2n), k-chunk 32, cp.async double buffer.
// __launch_bounds__(256, 2): cap regs at 128 -> 2 blocks/SM, single wave.
// ---------------------------------------------------------------------------
#define ATILE 10240
#define BUFB  (4 * ATILE)        // A limbs 0..1, B limbs 2..3
#define GEMM_SMEM (2 * BUFB)     // 81920

__device__ __forceinline__ void issue_tiles2(
    uint32_t sdst, const __nv_bfloat16* const* Ap, const __nv_bfloat16* const* Bp,
    int bm, int bn, int kc, int tid)
{
#pragma unroll
    for (int l = 0; l < 2; l++) {
#pragma unroll
        for (int r = 0; r < 2; r++) {
            int idx = tid + r * 256;
            int row = idx >> 2, q = idx & 3;
            uint32_t doff = (uint32_t)(row * 80 + q * 16);
            const void* sa = (const void*)(Ap[l] + (size_t)(bm + row) * DM + kc + q * 8);
            const void* sb = (const void*)(Bp[l] + (size_t)(bn + row) * DM + kc + q * 8);
            CP16(sdst + l * ATILE + doff, sa);
            CP16(sdst + (2 + l) * ATILE + doff, sb);
        }
    }
}

__global__ __launch_bounds__(256, 2) void gemm_hmma2(
    const __nv_bfloat16* __restrict__ Ah, const __nv_bfloat16* __restrict__ Am,
    const __nv_bfloat16* __restrict__ Bh, const __nv_bfloat16* __restrict__ Bm,
    const float* __restrict__ bias, float* __restrict__ C)
{
    extern __shared__ char smem[];
    const uint32_t sb = smem_u32(smem);
    const int tid = threadIdx.x;
    const int lane = tid & 31;
    const int wid = tid >> 5;
    const int wm = wid >> 1;
    const int wn = wid & 1;
    const int bm = blockIdx.y * 128;
    const int bn = blockIdx.x * 128;

    const __nv_bfloat16* Ap[2] = {Ah, Am};
    const __nv_bfloat16* Bp[2] = {Bh, Bm};

    float acc[2][8][4];
#pragma unroll
    for (int mi = 0; mi < 2; mi++)
#pragma unroll
        for (int hn = 0; hn < 8; hn++)
#pragma unroll
            for (int r = 0; r < 4; r++) acc[mi][hn][r] = 0.f;

    const uint32_t a_off = (uint32_t)((wm * 32 + (lane & 15)) * 80 + (lane >> 4) * 16);
    const uint32_t b_off = (uint32_t)((wn * 64 + (lane & 7) + (lane >> 4) * 8) * 80
                                      + ((lane >> 3) & 1) * 16);

    issue_tiles2(sb, Ap, Bp, bm, bn, 0, tid);
    CP_COMMIT();

    const int NCH = DM / 32;
    for (int c = 0; c < NCH; c++) {
        const uint32_t base = sb + (uint32_t)(c & 1) * BUFB;
        if (c + 1 < NCH) {
            issue_tiles2(sb + (uint32_t)((c + 1) & 1) * BUFB, Ap, Bp,
                         bm, bn, (c + 1) * 32, tid);
            CP_COMMIT();
            CP_WAIT(1);
        } else {
            CP_WAIT(0);
        }
        __syncthreads();

#pragma unroll
        for (int ks = 0; ks < 2; ks++) {
#pragma unroll
            for (int half = 0; half < 2; half++) {
                uint32_t bf[2][2][4];
#pragma unroll
                for (int lb = 0; lb < 2; lb++)
#pragma unroll
                    for (int g = 0; g < 2; g++)
                        ldsm4(bf[lb][g][0], bf[lb][g][1], bf[lb][g][2], bf[lb][g][3],
                              base + (2 + lb) * ATILE + b_off
                                   + (uint32_t)((half * 2 + g) * 16 * 80 + ks * 32));
#pragma unroll
                for (int la = 0; la < 2; la++) {
                    uint32_t af[2][4];
#pragma unroll
                    for (int mi = 0; mi < 2; mi++)
                        ldsm4(af[mi][0], af[mi][1], af[mi][2], af[mi][3],
                              base + la * ATILE + a_off
                                   + (uint32_t)(mi * 16 * 80 + ks * 32));
#pragma unroll
                    for (int lb = 0; lb < 2; lb++) {
                        if (la + lb < 2) {
#pragma unroll
                            for (int mi = 0; mi < 2; mi++)
#pragma unroll
                                for (int j = 0; j < 4; j++)
                                    mma16816(acc[mi][half * 4 + j], af[mi],
                                             bf[lb][j >> 1][(j & 1) * 2],
                                             bf[lb][j >> 1][(j & 1) * 2 + 1]);
                        }
                    }
                }
            }
        }
        __syncthreads();
    }

#pragma unroll
    for (int mi = 0; mi < 2; mi++) {
#pragma unroll
        for (int hn = 0; hn < 8; hn++) {
            int row = bm + wm * 32 + mi * 16 + (lane >> 2);
            int col = bn + wn * 64 + hn * 8 + (lane & 3) * 2;
            float b0 = bias[col], b1 = bias[col + 1];
            float2 o0 = make_float2(acc[mi][hn][0] + b0, acc[mi][hn][1] + b1);
            float2 o1 = make_float2(acc[mi][hn][2] + b0, acc[mi][hn][3] + b1);
            *(float2*)(C + (size_t)row * DM + col) = o0;
            *(float2*)(C + (size_t)(row + 8) * DM + col) = o1;
        }
    }
}

// ---------------------------------------------------------------------------
// Sorted top-16 insertion (lanes 0..15 hold desc-sorted (v,i); v[15]=min).
// ---------------------------------------------------------------------------
__device__ __forceinline__ void insert16(float& v, int& i, float cv, int cidx, int lane)
{
    unsigned keep = __ballot_sync(0xffffffffu,
        (lane < 16) && (v > cv || (v == cv && i < cidx)));
    int pos = __popc(keep & 0xffffu);
    float vu = __shfl_up_sync(0xffffffffu, v, 1);
    int   iu = __shfl_up_sync(0xffffffffu, i, 1);
    if (lane < 16) {
        if (lane == pos)      { v = cv; i = cidx; }
        else if (lane > pos)  { v = vu; i = iu;  }
    }
}

// ---------------------------------------------------------------------------
// Fused scores -> streaming top-16 -> softmax -> weights scatter ->
// attn = w @ V emitted as bf16 limbs. (Proven version, frozen.)
// ---------------------------------------------------------------------------
__global__ __launch_bounds__(256) void attn_topk_kernel(
    const float* __restrict__ Q, const float* __restrict__ K,
    const float* __restrict__ V, float* __restrict__ weights,
    __nv_bfloat16* __restrict__ Ah, __nv_bfloat16* __restrict__ Am)
{
    extern __shared__ float sm[];
    float* Qs = sm;                        // 64*68  [d][q]
    float* Ks = Qs + 64 * 68;              // 64*68  [d][key]
    float* Sc = Ks + 64 * 68;              // 64*68  [q][key]

    const int b = blockIdx.z;
    const int h = blockIdx.y;
    const int q0 = blockIdx.x * 64;
    const int tid = threadIdx.x;
    const int lane = tid & 31;
    const int wid = tid >> 5;
    const int tx = tid & 15;
    const int ty = tid >> 4;

#pragma unroll
    for (int r = 0; r < 4; r++) {
        int idx = tid + r * 256;
        int q = idx >> 4, c4 = idx & 15;
        float4 v = *(const float4*)(Q + (size_t)(b * S_ + q0 + q) * DM + h * DK + c4 * 4);
        Qs[(c4 * 4 + 0) * 68 + q] = v.x * 0.125f;
        Qs[(c4 * 4 + 1) * 68 + q] = v.y * 0.125f;
        Qs[(c4 * 4 + 2) * 68 + q] = v.z * 0.125f;
        Qs[(c4 * 4 + 3) * 68 + q] = v.w * 0.125f;
    }

    float tv[8];
    int   ti[8];
    float thr[8];
#pragma unroll
    for (int j = 0; j < 8; j++) { tv[j] = -INFINITY; ti[j] = 0x7fffffff; thr[j] = -INFINITY; }

    for (int k0 = 0; k0 < S_; k0 += 64) {
#pragma unroll
        for (int r = 0; r < 4; r++) {
            int idx = tid + r * 256;
            int key = idx >> 4, c4 = idx & 15;
            float4 v = *(const float4*)(K + (size_t)(b * S_ + k0 + key) * DM + h * DK + c4 * 4);
            Ks[(c4 * 4 + 0) * 68 + key] = v.x;
            Ks[(c4 * 4 + 1) * 68 + key] = v.y;
            Ks[(c4 * 4 + 2) * 68 + key] = v.z;
            Ks[(c4 * 4 + 3) * 68 + key] = v.w;
        }
        __syncthreads();

        unsigned long long acc[4][2];
#pragma unroll
        for (int i = 0; i < 4; i++) { acc[i][0] = 0ull; acc[i][1] = 0ull; }

#pragma unroll 16
        for (int kk = 0; kk < 64; kk++) {
            float4 a4 = *(const float4*)&Qs[kk * 68 + ty * 4];
            float4 b4 = *(const float4*)&Ks[kk * 68 + tx * 4];
            unsigned long long bp0 = pk2(b4.x, b4.y);
            unsigned long long bp1 = pk2(b4.z, b4.w);
            float a[4] = {a4.x, a4.y, a4.z, a4.w};
#pragma unroll
            for (int i = 0; i < 4; i++) {
                unsigned long long ap = pk2(a[i], a[i]);
                fma2(acc[i][0], ap, bp0);
                fma2(acc[i][1], ap, bp1);
            }
        }
#pragma unroll
        for (int i = 0; i < 4; i++) {
            float4 o;
            unpk2(acc[i][0], o.x, o.y);
            unpk2(acc[i][1], o.z, o.w);
            *(float4*)&Sc[(ty * 4 + i) * 68 + tx * 4] = o;
        }
        __syncthreads();

        float sv0[8], sv1[8];
#pragma unroll
        for (int j = 0; j < 8; j++) {
            int q = wid * 8 + j;
            sv0[j] = Sc[q * 68 + lane];
            sv1[j] = Sc[q * 68 + 32 + lane];
        }

#pragma unroll
        for (int j = 0; j < 8; j++) {
            unsigned m0 = __ballot_sync(0xffffffffu, sv0[j] > thr[j]);
            while (m0) {
                int src = __ffs(m0) - 1; m0 &= m0 - 1;
                float cv = __shfl_sync(0xffffffffu, sv0[j], src);
                if (cv > thr[j]) {
                    insert16(tv[j], ti[j], cv, k0 + src, lane);
                    thr[j] = __shfl_sync(0xffffffffu, tv[j], 15);
                }
            }
            unsigned m1 = __ballot_sync(0xffffffffu, sv1[j] > thr[j]);
            while (m1) {
                int src = __ffs(m1) - 1; m1 &= m1 - 1;
                float cv = __shfl_sync(0xffffffffu, sv1[j], src);
                if (cv > thr[j]) {
                    insert16(tv[j], ti[j], cv, k0 + 32 + src, lane);
                    thr[j] = __shfl_sync(0xffffffffu, tv[j], 15);
                }
            }
        }
    }

#pragma unroll
    for (int j = 0; j < 8; j++) {
        const int q = q0 + wid * 8 + j;
        float m = __shfl_sync(0xffffffffu, tv[j], 0);
        float e = (lane < 16) ? __expf(tv[j] - m) : 0.f;
        float s = e;
#pragma unroll
        for (int off = 8; off > 0; off >>= 1)
            s += __shfl_xor_sync(0xffffffffu, s, off);
        s = __shfl_sync(0xffffffffu, s, 0);
        float w = e / s;

        float* wrow = weights + ((size_t)((b * H_ + h) * S_) + q) * S_;
        if (lane < 16) wrow[ti[j]] = w;

        float a0 = 0.f, a1 = 0.f;
#pragma unroll
        for (int t = 0; t < TOPK_; t++) {
            float wt = __shfl_sync(0xffffffffu, w, t);
            int  idx = __shfl_sync(0xffffffffu, ti[j], t);
            const float* vr = V + (size_t)(b * S_ + idx) * DM + h * DK;
            a0 += wt * vr[lane];
            a1 += wt * vr[lane + 32];
        }
        size_t off0 = (size_t)(b * S_ + q) * DM + h * DK + lane;
        {
            __nv_bfloat16 hh = __float2bfloat16(a0);
            float r1 = a0 - __bfloat162float(hh);
            Ah[off0] = hh; Am[off0] = __float2bfloat16(r1);
        }
        {
            __nv_bfloat16 hh = __float2bfloat16(a1);
            float r1 = a1 - __bfloat162float(hh);
            Ah[off0 + 32] = hh; Am[off0 + 32] = __float2bfloat16(r1);
        }
    }
}

// ---------------------------------------------------------------------------
extern "C" void kernel_launch(void* const* d_in, const int* in_sizes, int n_in,
                              void* d_out, int out_size)
{
    const float* query = (const float*)d_in[0];
    const float* key   = (const float*)d_in[1];
    const float* value = (const float*)d_in[2];
    const float* Wq = (const float*)d_in[3];
    const float* bq = (const float*)d_in[4];
    const float* Wk = (const float*)d_in[5];
    const float* bk = (const float*)d_in[6];
    const float* Wv = (const float*)d_in[7];
    const float* bv = (const float*)d_in[8];
    const float* Wo = (const float*)d_in[9];
    const float* bo = (const float*)d_in[10];

    float* out = (float*)d_out;
    float* weights = out + (size_t)B_ * S_ * DM;

    float *Qp, *Kp, *Vp;
    cudaGetSymbolAddress((void**)&Qp, g_Q);
    cudaGetSymbolAddress((void**)&Kp, g_K);
    cudaGetSymbolAddress((void**)&Vp, g_V);
    __nv_bfloat16 *Ah, *Am, *Bh, *Bm, *Ch, *Cm;
    cudaGetSymbolAddress((void**)&Ah, g_Ah);
    cudaGetSymbolAddress((void**)&Am, g_Am);
    cudaGetSymbolAddress((void**)&Bh, g_Bh);
    cudaGetSymbolAddress((void**)&Bm, g_Bm);
    cudaGetSymbolAddress((void**)&Ch, g_Ch);
    cudaGetSymbolAddress((void**)&Cm, g_Cm);

    cudaFuncSetAttribute(gemm_hmma2,
                         cudaFuncAttributeMaxDynamicSharedMemorySize, GEMM_SMEM);
    dim3 ggrid(DM / 128, (B_ * S_) / 128);    // (8, 32)

    // 1. fused front: Q/K GEMMs + weights zero + all input-side splits
    fused_front<<<3072, 256>>>(query, Wq, bq, Qp,
                               key, Wk, bk, Kp,
                               value, Ah, Am,
                               Wv, Bh, Bm,
                               Wo, Ch, Cm,
                               (float4*)weights);

    // 2. V projection: HMMA 2-limb
    gemm_hmma2<<<ggrid, 256, GEMM_SMEM>>>(Ah, Am, Bh, Bm, bv, Vp);

    // 3. fused attention (writes weights + attn-output limbs into A buffers)
    size_t smem = (size_t)(3 * 64 * 68) * sizeof(float);
    cudaFuncSetAttribute(attn_topk_kernel,
                         cudaFuncAttributeMaxDynamicSharedMemorySize, (int)smem);
    dim3 attn_grid(S_ / 64, H_, B_);
    attn_topk_kernel<<<attn_grid, 256, smem>>>(Qp, Kp, Vp, weights, Ah, Am);

    // 4. output projection: HMMA 2-limb
    gemm_hmma2<<<ggrid, 256, GEMM_SMEM>>>(Ah, Am, Ch, Cm, bo, out);
}

// round 17
// speedup vs baseline: 1.3400x; 1.0086x over previous
#include <cuda_runtime.h>
#include <cuda_bf16.h>
#include <math.h>
#include <stdint.h>

#define B_    2
#define S_    2048
#define DM    1024
#define H_    16
#define DK    64
#define TOPK_ 16

// Scratch (allocation-free rule: __device__ globals)
__device__ float g_Q[B_ * S_ * DM];
__device__ float g_K[B_ * S_ * DM];
__device__ float g_V[B_ * S_ * DM];
// top-16 results per (b,h,q): softmaxed weight + key index
__device__ float g_topw[B_ * H_ * S_ * TOPK_];
__device__ int   g_topi[B_ * H_ * S_ * TOPK_];
// bf16 limb buffers: A (activations), B (Wv), C (Wo)
__device__ __nv_bfloat16 g_Ah[B_ * S_ * DM];
__device__ __nv_bfloat16 g_Am[B_ * S_ * DM];
__device__ __nv_bfloat16 g_Bh[DM * DM];
__device__ __nv_bfloat16 g_Bm[DM * DM];
__device__ __nv_bfloat16 g_Ch[DM * DM];
__device__ __nv_bfloat16 g_Cm[DM * DM];

// ============================ PTX helpers (sm_80+ only) ============================
__device__ __forceinline__ uint32_t smem_u32(const void* p) {
    uint32_t a;
    asm("{ .reg .u64 t; cvta.to.shared.u64 t, %1; cvt.u32.u64 %0, t; }"
        : "=r"(a) : "l"(p));
    return a;
}
#define CP16(dst, src) \
    asm volatile("cp.async.cg.shared.global [%0], [%1], 16;" :: "r"(dst), "l"(src))
#define CP_COMMIT() asm volatile("cp.async.commit_group;" ::: "memory")
#define CP_WAIT(n)  asm volatile("cp.async.wait_group %0;" :: "n"(n) : "memory")

__device__ __forceinline__ void ldsm4(uint32_t& r0, uint32_t& r1, uint32_t& r2,
                                      uint32_t& r3, uint32_t a) {
    asm volatile("ldmatrix.sync.aligned.m8n8.x4.shared.b16 {%0,%1,%2,%3}, [%4];"
                 : "=r"(r0), "=r"(r1), "=r"(r2), "=r"(r3) : "r"(a));
}
__device__ __forceinline__ void mma16816(float* c, const uint32_t* a,
                                         uint32_t b0, uint32_t b1) {
    asm volatile(
        "mma.sync.aligned.m16n8k16.row.col.f32.bf16.bf16.f32 "
        "{%0,%1,%2,%3}, {%4,%5,%6,%7}, {%8,%9}, {%0,%1,%2,%3};"
        : "+f"(c[0]), "+f"(c[1]), "+f"(c[2]), "+f"(c[3])
        : "r"(a[0]), "r"(a[1]), "r"(a[2]), "r"(a[3]), "r"(b0), "r"(b1));
}

// ---- packed fp32x2 helpers ----
__device__ __forceinline__ unsigned long long pk2(float x, float y) {
    unsigned long long r;
    asm("mov.b64 %0, {%1, %2};" : "=l"(r) : "f"(x), "f"(y));
    return r;
}
__device__ __forceinline__ void fma2(unsigned long long& d,
                                     unsigned long long a, unsigned long long b) {
    asm("fma.rn.f32x2 %0, %1, %2, %0;" : "+l"(d) : "l"(a), "l"(b));
}
__device__ __forceinline__ void unpk2(unsigned long long v, float& lo, float& hi) {
    asm("mov.b64 {%0, %1}, %2;" : "=f"(lo), "=f"(hi) : "l"(v));
}

// ---------------------------------------------------------------------------
// Fused front kernel: one launch, 3072 blocks.
// ---------------------------------------------------------------------------
__global__ __launch_bounds__(256, 2) void fused_front(
    const float* __restrict__ query, const float* __restrict__ Wq,
    const float* __restrict__ bq, float* __restrict__ Qout,
    const float* __restrict__ key, const float* __restrict__ Wk,
    const float* __restrict__ bk, float* __restrict__ Kout,
    const float* __restrict__ value,
    __nv_bfloat16* __restrict__ Ah, __nv_bfloat16* __restrict__ Am,
    const float* __restrict__ Wv,
    __nv_bfloat16* __restrict__ Bh, __nv_bfloat16* __restrict__ Bm,
    const float* __restrict__ Wo,
    __nv_bfloat16* __restrict__ Ch, __nv_bfloat16* __restrict__ Cm,
    float4* __restrict__ wz)
{
    __shared__ float As[16][132];
    __shared__ float Ws[16][132];

    const int id = blockIdx.x;
    const int tid = threadIdx.x;

    if (id < 512) {
        const float *A, *W, *bias;
        float* C;
        if (id < 256) { A = query; W = Wq; bias = bq; C = Qout; }
        else          { A = key;   W = Wk; bias = bk; C = Kout; }
        const int r = id & 255;
        const int bm = (r >> 3) * 128;
        const int bn = (r & 7) * 128;
        const int tx = tid & 15;
        const int ty = tid >> 4;

        float acc[8][8];
#pragma unroll
        for (int i = 0; i < 8; i++)
#pragma unroll
            for (int j = 0; j < 8; j++) acc[i][j] = 0.f;

        for (int k0 = 0; k0 < DM; k0 += 16) {
#pragma unroll
            for (int rr = 0; rr < 2; rr++) {
                int idx = tid + rr * 256;
                int row = idx >> 2;
                int c4  = idx & 3;
                float4 av = *(const float4*)(A + (size_t)(bm + row) * DM + k0 + c4 * 4);
                float4 wv = *(const float4*)(W + (size_t)(bn + row) * DM + k0 + c4 * 4);
                As[c4 * 4 + 0][row] = av.x; As[c4 * 4 + 1][row] = av.y;
                As[c4 * 4 + 2][row] = av.z; As[c4 * 4 + 3][row] = av.w;
                Ws[c4 * 4 + 0][row] = wv.x; Ws[c4 * 4 + 1][row] = wv.y;
                Ws[c4 * 4 + 2][row] = wv.z; Ws[c4 * 4 + 3][row] = wv.w;
            }
            __syncthreads();

#pragma unroll
            for (int kk = 0; kk < 16; kk++) {
                float4 a0 = *(const float4*)&As[kk][ty * 8];
                float4 a1 = *(const float4*)&As[kk][ty * 8 + 4];
                float4 b0 = *(const float4*)&Ws[kk][tx * 8];
                float4 b1 = *(const float4*)&Ws[kk][tx * 8 + 4];
                float a[8] = {a0.x, a0.y, a0.z, a0.w, a1.x, a1.y, a1.z, a1.w};
                float b[8] = {b0.x, b0.y, b0.z, b0.w, b1.x, b1.y, b1.z, b1.w};
#pragma unroll
                for (int i = 0; i < 8; i++)
#pragma unroll
                    for (int j = 0; j < 8; j++) acc[i][j] += a[i] * b[j];
            }
            __syncthreads();
        }

#pragma unroll
        for (int i = 0; i < 8; i++) {
            float* crow = C + (size_t)(bm + ty * 8 + i) * DM + bn + tx * 8;
#pragma unroll
            for (int j4 = 0; j4 < 2; j4++) {
                float4 o;
                o.x = acc[i][j4 * 4 + 0] + bias[bn + tx * 8 + j4 * 4 + 0];
                o.y = acc[i][j4 * 4 + 1] + bias[bn + tx * 8 + j4 * 4 + 1];
                o.z = acc[i][j4 * 4 + 2] + bias[bn + tx * 8 + j4 * 4 + 2];
                o.w = acc[i][j4 * 4 + 3] + bias[bn + tx * 8 + j4 * 4 + 3];
                *(float4*)(crow + j4 * 4) = o;
            }
        }
    } else if (id < 1024) {
        const size_t n4 = (size_t)B_ * H_ * S_ * S_ / 4;
        size_t i = (size_t)(id - 512) * 256 + tid;
        const size_t stride = (size_t)512 * 256;
        float4 z = make_float4(0.f, 0.f, 0.f, 0.f);
        for (; i < n4; i += stride) wz[i] = z;
    } else {
        const float* x;
        __nv_bfloat16 *h, *m;
        int n, base, nb;
        if (id < 2048)      { x = value; h = Ah; m = Am;
                              n = B_ * S_ * DM; base = 1024; nb = 1024; }
        else if (id < 2560) { x = Wv; h = Bh; m = Bm;
                              n = DM * DM; base = 2048; nb = 512; }
        else                { x = Wo; h = Ch; m = Cm;
                              n = DM * DM; base = 2560; nb = 512; }
        int i = (id - base) * 256 + tid;
        int stride = nb * 256;
        for (; i < n; i += stride) {
            float v = x[i];
            __nv_bfloat16 hh = __float2bfloat16(v);
            float r1 = v - __bfloat162float(hh);
            h[i] = hh; m[i] = __float2bfloat16(r1);
        }
    }
}

// ---------------------------------------------------------------------------
// HMMA GEMM (2-limb, 3 products hh+hm+mh). CTA 128x128, 8 warps, k-chunk 32,
// cp.async double buffer, __launch_bounds__(256,2) -> 128 regs, 2 blocks/SM.
// ---------------------------------------------------------------------------
#define ATILE 10240
#define BUFB  (4 * ATILE)
#define GEMM_SMEM (2 * BUFB)     // 81920

__device__ __forceinline__ void issue_tiles2(
    uint32_t sdst, const __nv_bfloat16* const* Ap, const __nv_bfloat16* const* Bp,
    int bm, int bn, int kc, int tid)
{
#pragma unroll
    for (int l = 0; l < 2; l++) {
#pragma unroll
        for (int r = 0; r < 2; r++) {
            int idx = tid + r * 256;
            int row = idx >> 2, q = idx & 3;
            uint32_t doff = (uint32_t)(row * 80 + q * 16);
            const void* sa = (const void*)(Ap[l] + (size_t)(bm + row) * DM + kc + q * 8);
            const void* sb = (const void*)(Bp[l] + (size_t)(bn + row) * DM + kc + q * 8);
            CP16(sdst + l * ATILE + doff, sa);
            CP16(sdst + (2 + l) * ATILE + doff, sb);
        }
    }
}

__global__ __launch_bounds__(256, 2) void gemm_hmma2(
    const __nv_bfloat16* __restrict__ Ah, const __nv_bfloat16* __restrict__ Am,
    const __nv_bfloat16* __restrict__ Bh, const __nv_bfloat16* __restrict__ Bm,
    const float* __restrict__ bias, float* __restrict__ C)
{
    extern __shared__ char smem[];
    const uint32_t sb = smem_u32(smem);
    const int tid = threadIdx.x;
    const int lane = tid & 31;
    const int wid = tid >> 5;
    const int wm = wid >> 1;
    const int wn = wid & 1;
    const int bm = blockIdx.y * 128;
    const int bn = blockIdx.x * 128;

    const __nv_bfloat16* Ap[2] = {Ah, Am};
    const __nv_bfloat16* Bp[2] = {Bh, Bm};

    float acc[2][8][4];
#pragma unroll
    for (int mi = 0; mi < 2; mi++)
#pragma unroll
        for (int hn = 0; hn < 8; hn++)
#pragma unroll
            for (int r = 0; r < 4; r++) acc[mi][hn][r] = 0.f;

    const uint32_t a_off = (uint32_t)((wm * 32 + (lane & 15)) * 80 + (lane >> 4) * 16);
    const uint32_t b_off = (uint32_t)((wn * 64 + (lane & 7) + (lane >> 4) * 8) * 80
                                      + ((lane >> 3) & 1) * 16);

    issue_tiles2(sb, Ap, Bp, bm, bn, 0, tid);
    CP_COMMIT();

    const int NCH = DM / 32;
    for (int c = 0; c < NCH; c++) {
        const uint32_t base = sb + (uint32_t)(c & 1) * BUFB;
        if (c + 1 < NCH) {
            issue_tiles2(sb + (uint32_t)((c + 1) & 1) * BUFB, Ap, Bp,
                         bm, bn, (c + 1) * 32, tid);
            CP_COMMIT();
            CP_WAIT(1);
        } else {
            CP_WAIT(0);
        }
        __syncthreads();

#pragma unroll
        for (int ks = 0; ks < 2; ks++) {
#pragma unroll
            for (int half = 0; half < 2; half++) {
                uint32_t bf[2][2][4];
#pragma unroll
                for (int lb = 0; lb < 2; lb++)
#pragma unroll
                    for (int g = 0; g < 2; g++)
                        ldsm4(bf[lb][g][0], bf[lb][g][1], bf[lb][g][2], bf[lb][g][3],
                              base + (2 + lb) * ATILE + b_off
                                   + (uint32_t)((half * 2 + g) * 16 * 80 + ks * 32));
#pragma unroll
                for (int la = 0; la < 2; la++) {
                    uint32_t af[2][4];
#pragma unroll
                    for (int mi = 0; mi < 2; mi++)
                        ldsm4(af[mi][0], af[mi][1], af[mi][2], af[mi][3],
                              base + la * ATILE + a_off
                                   + (uint32_t)(mi * 16 * 80 + ks * 32));
#pragma unroll
                    for (int lb = 0; lb < 2; lb++) {
                        if (la + lb < 2) {
#pragma unroll
                            for (int mi = 0; mi < 2; mi++)
#pragma unroll
                                for (int j = 0; j < 4; j++)
                                    mma16816(acc[mi][half * 4 + j], af[mi],
                                             bf[lb][j >> 1][(j & 1) * 2],
                                             bf[lb][j >> 1][(j & 1) * 2 + 1]);
                        }
                    }
                }
            }
        }
        __syncthreads();
    }

#pragma unroll
    for (int mi = 0; mi < 2; mi++) {
#pragma unroll
        for (int hn = 0; hn < 8; hn++) {
            int row = bm + wm * 32 + mi * 16 + (lane >> 2);
            int col = bn + wn * 64 + hn * 8 + (lane & 3) * 2;
            float b0 = bias[col], b1 = bias[col + 1];
            float2 o0 = make_float2(acc[mi][hn][0] + b0, acc[mi][hn][1] + b1);
            float2 o1 = make_float2(acc[mi][hn][2] + b0, acc[mi][hn][3] + b1);
            *(float2*)(C + (size_t)row * DM + col) = o0;
            *(float2*)(C + (size_t)(row + 8) * DM + col) = o1;
        }
    }
}

// ---------------------------------------------------------------------------
// Sorted top-16 insertion (lanes 0..15 hold desc-sorted (v,i); v[15]=min).
// ---------------------------------------------------------------------------
__device__ __forceinline__ void insert16(float& v, int& i, float cv, int cidx, int lane)
{
    unsigned keep = __ballot_sync(0xffffffffu,
        (lane < 16) && (v > cv || (v == cv && i < cidx)));
    int pos = __popc(keep & 0xffffu);
    float vu = __shfl_up_sync(0xffffffffu, v, 1);
    int   iu = __shfl_up_sync(0xffffffffu, i, 1);
    if (lane < 16) {
        if (lane == pos)      { v = cv; i = cidx; }
        else if (lane > pos)  { v = vu; i = iu;  }
    }
}

// ---------------------------------------------------------------------------
// attn_scores: scores GEMM -> streaming top-16 -> softmax -> weights scatter
//              -> store (w, idx) x16 per query. Does NOT touch V.
// (Launched 2nd in the call so ncu -s 5 profiles it.)
// ---------------------------------------------------------------------------
__global__ __launch_bounds__(256) void attn_scores_kernel(
    const float* __restrict__ Q, const float* __restrict__ K,
    float* __restrict__ weights,
    float* __restrict__ topw, int* __restrict__ topidx)
{
    extern __shared__ float sm[];
    float* Qs = sm;                        // 64*68  [d][q]
    float* Ks = Qs + 64 * 68;              // 64*68  [d][key]
    float* Sc = Ks + 64 * 68;              // 64*68  [q][key]

    const int b = blockIdx.z;
    const int h = blockIdx.y;
    const int q0 = blockIdx.x * 64;
    const int tid = threadIdx.x;
    const int lane = tid & 31;
    const int wid = tid >> 5;
    const int tx = tid & 15;
    const int ty = tid >> 4;

#pragma unroll
    for (int r = 0; r < 4; r++) {
        int idx = tid + r * 256;
        int q = idx >> 4, c4 = idx & 15;
        float4 v = *(const float4*)(Q + (size_t)(b * S_ + q0 + q) * DM + h * DK + c4 * 4);
        Qs[(c4 * 4 + 0) * 68 + q] = v.x * 0.125f;
        Qs[(c4 * 4 + 1) * 68 + q] = v.y * 0.125f;
        Qs[(c4 * 4 + 2) * 68 + q] = v.z * 0.125f;
        Qs[(c4 * 4 + 3) * 68 + q] = v.w * 0.125f;
    }

    float tv[8];
    int   ti[8];
    float thr[8];
#pragma unroll
    for (int j = 0; j < 8; j++) { tv[j] = -INFINITY; ti[j] = 0x7fffffff; thr[j] = -INFINITY; }

    for (int k0 = 0; k0 < S_; k0 += 64) {
#pragma unroll
        for (int r = 0; r < 4; r++) {
            int idx = tid + r * 256;
            int key = idx >> 4, c4 = idx & 15;
            float4 v = *(const float4*)(K + (size_t)(b * S_ + k0 + key) * DM + h * DK + c4 * 4);
            Ks[(c4 * 4 + 0) * 68 + key] = v.x;
            Ks[(c4 * 4 + 1) * 68 + key] = v.y;
            Ks[(c4 * 4 + 2) * 68 + key] = v.z;
            Ks[(c4 * 4 + 3) * 68 + key] = v.w;
        }
        __syncthreads();

        unsigned long long acc[4][2];
#pragma unroll
        for (int i = 0; i < 4; i++) { acc[i][0] = 0ull; acc[i][1] = 0ull; }

#pragma unroll 16
        for (int kk = 0; kk < 64; kk++) {
            float4 a4 = *(const float4*)&Qs[kk * 68 + ty * 4];
            float4 b4 = *(const float4*)&Ks[kk * 68 + tx * 4];
            unsigned long long bp0 = pk2(b4.x, b4.y);
            unsigned long long bp1 = pk2(b4.z, b4.w);
            float a[4] = {a4.x, a4.y, a4.z, a4.w};
#pragma unroll
            for (int i = 0; i < 4; i++) {
                unsigned long long ap = pk2(a[i], a[i]);
                fma2(acc[i][0], ap, bp0);
                fma2(acc[i][1], ap, bp1);
            }
        }
#pragma unroll
        for (int i = 0; i < 4; i++) {
            float4 o;
            unpk2(acc[i][0], o.x, o.y);
            unpk2(acc[i][1], o.z, o.w);
            *(float4*)&Sc[(ty * 4 + i) * 68 + tx * 4] = o;
        }
        __syncthreads();

        float sv0[8], sv1[8];
#pragma unroll
        for (int j = 0; j < 8; j++) {
            int q = wid * 8 + j;
            sv0[j] = Sc[q * 68 + lane];
            sv1[j] = Sc[q * 68 + 32 + lane];
        }

#pragma unroll
        for (int j = 0; j < 8; j++) {
            unsigned m0 = __ballot_sync(0xffffffffu, sv0[j] > thr[j]);
            while (m0) {
                int src = __ffs(m0) - 1; m0 &= m0 - 1;
                float cv = __shfl_sync(0xffffffffu, sv0[j], src);
                if (cv > thr[j]) {
                    insert16(tv[j], ti[j], cv, k0 + src, lane);
                    thr[j] = __shfl_sync(0xffffffffu, tv[j], 15);
                }
            }
            unsigned m1 = __ballot_sync(0xffffffffu, sv1[j] > thr[j]);
            while (m1) {
                int src = __ffs(m1) - 1; m1 &= m1 - 1;
                float cv = __shfl_sync(0xffffffffu, sv1[j], src);
                if (cv > thr[j]) {
                    insert16(tv[j], ti[j], cv, k0 + 32 + src, lane);
                    thr[j] = __shfl_sync(0xffffffffu, tv[j], 15);
                }
            }
        }
    }

    // softmax + weights scatter + store (w, idx)
#pragma unroll
    for (int j = 0; j < 8; j++) {
        const int q = q0 + wid * 8 + j;
        float m = __shfl_sync(0xffffffffu, tv[j], 0);
        float e = (lane < 16) ? __expf(tv[j] - m) : 0.f;
        float s = e;
#pragma unroll
        for (int off = 8; off > 0; off >>= 1)
            s += __shfl_xor_sync(0xffffffffu, s, off);
        s = __shfl_sync(0xffffffffu, s, 0);
        float w = e / s;

        size_t row = (size_t)((b * H_ + h) * S_) + q;
        float* wrow = weights + row * S_;
        if (lane < 16) {
            wrow[ti[j]] = w;
            topw[row * TOPK_ + lane] = w;
            topidx[row * TOPK_ + lane] = ti[j];
        }
    }
}

// ---------------------------------------------------------------------------
// attn_gather: attn = w @ V, emitted directly as bf16 limbs.
// grid (S/64, H, B), 8 warps x 8 queries, same mapping as scores epilogue.
// ---------------------------------------------------------------------------
__global__ __launch_bounds__(256) void attn_gather_kernel(
    const float* __restrict__ V,
    const float* __restrict__ topw, const int* __restrict__ topidx,
    __nv_bfloat16* __restrict__ Ah, __nv_bfloat16* __restrict__ Am)
{
    const int b = blockIdx.z;
    const int h = blockIdx.y;
    const int q0 = blockIdx.x * 64;
    const int tid = threadIdx.x;
    const int lane = tid & 31;
    const int wid = tid >> 5;

#pragma unroll
    for (int j = 0; j < 8; j++) {
        const int q = q0 + wid * 8 + j;
        size_t row = (size_t)((b * H_ + h) * S_) + q;
        float w = (lane < 16) ? topw[row * TOPK_ + lane] : 0.f;
        int  id = (lane < 16) ? topidx[row * TOPK_ + lane] : 0;

        float a0 = 0.f, a1 = 0.f;
#pragma unroll
        for (int t = 0; t < TOPK_; t++) {
            float wt = __shfl_sync(0xffffffffu, w, t);
            int  idx = __shfl_sync(0xffffffffu, id, t);
            const float* vr = V + (size_t)(b * S_ + idx) * DM + h * DK;
            a0 += wt * vr[lane];
            a1 += wt * vr[lane + 32];
        }
        size_t off0 = (size_t)(b * S_ + q) * DM + h * DK + lane;
        {
            __nv_bfloat16 hh = __float2bfloat16(a0);
            float r1 = a0 - __bfloat162float(hh);
            Ah[off0] = hh; Am[off0] = __float2bfloat16(r1);
        }
        {
            __nv_bfloat16 hh = __float2bfloat16(a1);
            float r1 = a1 - __bfloat162float(hh);
            Ah[off0 + 32] = hh; Am[off0 + 32] = __float2bfloat16(r1);
        }
    }
}

// ---------------------------------------------------------------------------
extern "C" void kernel_launch(void* const* d_in, const int* in_sizes, int n_in,
                              void* d_out, int out_size)
{
    const float* query = (const float*)d_in[0];
    const float* key   = (const float*)d_in[1];
    const float* value = (const float*)d_in[2];
    const float* Wq = (const float*)d_in[3];
    const float* bq = (const float*)d_in[4];
    const float* Wk = (const float*)d_in[5];
    const float* bk = (const float*)d_in[6];
    const float* Wv = (const float*)d_in[7];
    const float* bv = (const float*)d_in[8];
    const float* Wo = (const float*)d_in[9];
    const float* bo = (const float*)d_in[10];

    float* out = (float*)d_out;
    float* weights = out + (size_t)B_ * S_ * DM;

    float *Qp, *Kp, *Vp, *topw;
    int* topidx;
    cudaGetSymbolAddress((void**)&Qp, g_Q);
    cudaGetSymbolAddress((void**)&Kp, g_K);
    cudaGetSymbolAddress((void**)&Vp, g_V);
    cudaGetSymbolAddress((void**)&topw, g_topw);
    cudaGetSymbolAddress((void**)&topidx, g_topi);
    __nv_bfloat16 *Ah, *Am, *Bh, *Bm, *Ch, *Cm;
    cudaGetSymbolAddress((void**)&Ah, g_Ah);
    cudaGetSymbolAddress((void**)&Am, g_Am);
    cudaGetSymbolAddress((void**)&Bh, g_Bh);
    cudaGetSymbolAddress((void**)&Bm, g_Bm);
    cudaGetSymbolAddress((void**)&Ch, g_Ch);
    cudaGetSymbolAddress((void**)&Cm, g_Cm);

    cudaFuncSetAttribute(gemm_hmma2,
                         cudaFuncAttributeMaxDynamicSharedMemorySize, GEMM_SMEM);
    dim3 ggrid(DM / 128, (B_ * S_) / 128);    // (8, 32)
    dim3 attn_grid(S_ / 64, H_, B_);          // (32, 16, 2)

    // 1. fused front: Q/K GEMMs + weights zero + all input-side splits
    fused_front<<<3072, 256>>>(query, Wq, bq, Qp,
                               key, Wk, bk, Kp,
                               value, Ah, Am,
                               Wv, Bh, Bm,
                               Wo, Ch, Cm,
                               (float4*)weights);

    // 2. attention scores + top-16 + softmax + weights scatter (profiled slot)
    size_t smem = (size_t)(3 * 64 * 68) * sizeof(float);
    cudaFuncSetAttribute(attn_scores_kernel,
                         cudaFuncAttributeMaxDynamicSharedMemorySize, (int)smem);
    attn_scores_kernel<<<attn_grid, 256, smem>>>(Qp, Kp, weights, topw, topidx);

    // 3. V projection: HMMA 2-limb
    gemm_hmma2<<<ggrid, 256, GEMM_SMEM>>>(Ah, Am, Bh, Bm, bv, Vp);

    // 4. gather: attn = w @ V -> bf16 limbs
    attn_gather_kernel<<<attn_grid, 256>>>(Vp, topw, topidx, Ah, Am);

    // 5. output projection: HMMA 2-limb
    gemm_hmma2<<<ggrid, 256, GEMM_SMEM>>>(Ah, Am, Ch, Cm, bo, out);
}